// round 1
// baseline (speedup 1.0000x reference)
#include <cuda_runtime.h>
#include <cuda_bf16.h>
#include <cstdint>

// Problem dims (fixed by the reference)
#define M_TOT 4096            // 2*2048
#define N_TOT 11008
#define K_TOT 4096
#define QW_COLS (N_TOT / 8)   // 1376 packed int32 per k-row
#define GROUP 128

// Tiling
#define BM 128
#define BN 64
#define BK 32
#define TM 8
#define TN 4
#define THREADS 256

__global__ __launch_bounds__(THREADS) void gemm_dq_kernel(
    const float* __restrict__ A,        // [M_TOT, K_TOT]
    const unsigned* __restrict__ QW,    // [K_TOT, QW_COLS]
    const unsigned* __restrict__ QZ,    // [K_TOT/GROUP, QW_COLS]
    const float* __restrict__ SC,       // [K_TOT/GROUP, N_TOT]
    float* __restrict__ C)              // [M_TOT, N_TOT]
{
    __shared__ __align__(16) float As[BK][BM + 4];  // A stored transposed: As[k][m]
    __shared__ __align__(16) float Bs[BK][BN + 4];  // dequantized weights: Bs[k][n]

    const int tid = threadIdx.x;
    const int bm = blockIdx.y * BM;
    const int bn = blockIdx.x * BN;

    const int tx = tid & 15;   // n-direction (16)
    const int ty = tid >> 4;   // m-direction (16)

    // A loading: each thread loads 4 float4 (row = arow + 32*i, k-quad = akv)
    const int arow = tid >> 3;   // 0..31
    const int akv  = tid & 7;    // 0..7

    // B dequant: each thread handles one packed int32 word (8 nibbles)
    const int bk_  = tid >> 3;   // k within tile, 0..31
    const int bw   = tid & 7;    // word within the 64-col span
    const int ncol = bn + bw * 8;

    float acc[TM][TN];
    #pragma unroll
    for (int i = 0; i < TM; i++)
        #pragma unroll
        for (int j = 0; j < TN; j++) acc[i][j] = 0.f;

    for (int k0 = 0; k0 < K_TOT; k0 += BK) {
        // ---- load A tile (BM x BK), store k-major ----
        #pragma unroll
        for (int i = 0; i < 4; i++) {
            const int m = arow + 32 * i;
            const float4 v = *reinterpret_cast<const float4*>(
                &A[(size_t)(bm + m) * K_TOT + k0 + akv * 4]);
            As[akv * 4 + 0][m] = v.x;
            As[akv * 4 + 1][m] = v.y;
            As[akv * 4 + 2][m] = v.z;
            As[akv * 4 + 3][m] = v.w;
        }

        // ---- dequantize B tile (BK x BN) ----
        {
            const int g = k0 >> 7;  // whole BK chunk lies in one group (32 | k0, GROUP=128)
            const unsigned qw = QW[(size_t)(k0 + bk_) * QW_COLS + (ncol >> 3)];
            const unsigned qz = QZ[(size_t)g * QW_COLS + (ncol >> 3)];
            const float* scp = &SC[(size_t)g * N_TOT + ncol];
            #pragma unroll
            for (int j = 0; j < 8; j++) {
                const int w = (int)((qw >> (4 * j)) & 15u) - (int)((qz >> (4 * j)) & 15u);
                Bs[bk_][bw * 8 + j] = (float)w * scp[j];
            }
        }
        __syncthreads();

        // ---- compute ----
        #pragma unroll
        for (int kk = 0; kk < BK; kk++) {
            const float4 a0 = *reinterpret_cast<const float4*>(&As[kk][ty * TM]);
            const float4 a1 = *reinterpret_cast<const float4*>(&As[kk][ty * TM + 4]);
            const float4 b0 = *reinterpret_cast<const float4*>(&Bs[kk][tx * TN]);
            const float a[TM] = {a0.x, a0.y, a0.z, a0.w, a1.x, a1.y, a1.z, a1.w};
            const float b[TN] = {b0.x, b0.y, b0.z, b0.w};
            #pragma unroll
            for (int i = 0; i < TM; i++)
                #pragma unroll
                for (int j = 0; j < TN; j++)
                    acc[i][j] = fmaf(a[i], b[j], acc[i][j]);
        }
        __syncthreads();
    }

    // ---- epilogue: vectorized fp32 stores ----
    #pragma unroll
    for (int i = 0; i < TM; i++) {
        const float4 v = make_float4(acc[i][0], acc[i][1], acc[i][2], acc[i][3]);
        *reinterpret_cast<float4*>(
            &C[(size_t)(bm + ty * TM + i) * N_TOT + bn + tx * TN]) = v;
    }
}

extern "C" void kernel_launch(void* const* d_in, const int* in_sizes, int n_in,
                              void* d_out, int out_size)
{
    const float*    A  = (const float*)d_in[0];     // input   (2,2048,4096) f32
    const unsigned* QW = (const unsigned*)d_in[1];  // qweight (4096,1376)  i32
    const unsigned* QZ = (const unsigned*)d_in[2];  // qzeros  (32,1376)    i32
    const float*    SC = (const float*)d_in[3];     // scales  (32,11008)   f32
    float*          C  = (float*)d_out;             // (2,2048,11008)       f32

    dim3 grid(N_TOT / BN, M_TOT / BM);  // (172, 32)
    gemm_dq_kernel<<<grid, THREADS>>>(A, QW, QZ, SC, C);
}

// round 3
// speedup vs baseline: 1.7068x; 1.7068x over previous
#include <cuda_runtime.h>
#include <cuda_bf16.h>
#include <cstdint>

#define M_TOT 4096
#define N_TOT 11008
#define K_TOT 4096
#define QWC   1376            // N_TOT/8 packed words per k-row

#define BM 128
#define BN 128
#define BK 64
#define NCH (K_TOT / BK)      // 64
#define THREADS 256

// dynamic smem layout (bytes)
#define STG_BYTES 65536
#define OFF_AH 0
#define OFF_AL 16384
#define OFF_BH 32768
#define OFF_BL 49152
#define OFF_SC 131072                 // 32 groups x 128 n floats = 16KB
#define SMEM_TOTAL (131072 + 16384)

__device__ __forceinline__ uint32_t smem_u32(const void* p) {
    uint32_t a;
    asm("{ .reg .u64 t; cvta.to.shared.u64 t, %1; cvt.u32.u64 %0, t; }"
        : "=r"(a) : "l"(p));
    return a;
}

__device__ __forceinline__ void ldsm4(uint32_t* r, uint32_t addr) {
    asm volatile("ldmatrix.sync.aligned.m8n8.x4.shared.b16 {%0,%1,%2,%3}, [%4];"
                 : "=r"(r[0]), "=r"(r[1]), "=r"(r[2]), "=r"(r[3]) : "r"(addr));
}
__device__ __forceinline__ void ldsm4t(uint32_t* r, uint32_t addr) {
    asm volatile("ldmatrix.sync.aligned.m8n8.x4.trans.shared.b16 {%0,%1,%2,%3}, [%4];"
                 : "=r"(r[0]), "=r"(r[1]), "=r"(r[2]), "=r"(r[3]) : "r"(addr));
}
__device__ __forceinline__ void mma_bf16(float* d, const uint32_t* a, const uint32_t* b) {
    asm volatile(
        "mma.sync.aligned.m16n8k16.row.col.f32.bf16.bf16.f32 "
        "{%0,%1,%2,%3}, {%4,%5,%6,%7}, {%8,%9}, {%0,%1,%2,%3};"
        : "+f"(d[0]), "+f"(d[1]), "+f"(d[2]), "+f"(d[3])
        : "r"(a[0]), "r"(a[1]), "r"(a[2]), "r"(a[3]), "r"(b[0]), "r"(b[1]));
}

// pack 8 floats (one 16B smem chunk) into bf16 hi + bf16 lo uint4s
__device__ __forceinline__ void cvt_hilo(const float4& v0, const float4& v1,
                                         uint4& hi, uint4& lo) {
    __nv_bfloat162 h0 = __floats2bfloat162_rn(v0.x, v0.y);
    __nv_bfloat162 h1 = __floats2bfloat162_rn(v0.z, v0.w);
    __nv_bfloat162 h2 = __floats2bfloat162_rn(v1.x, v1.y);
    __nv_bfloat162 h3 = __floats2bfloat162_rn(v1.z, v1.w);
    __nv_bfloat162 l0 = __floats2bfloat162_rn(v0.x - __bfloat162float(h0.x),
                                              v0.y - __bfloat162float(h0.y));
    __nv_bfloat162 l1 = __floats2bfloat162_rn(v0.z - __bfloat162float(h1.x),
                                              v0.w - __bfloat162float(h1.y));
    __nv_bfloat162 l2 = __floats2bfloat162_rn(v1.x - __bfloat162float(h2.x),
                                              v1.y - __bfloat162float(h2.y));
    __nv_bfloat162 l3 = __floats2bfloat162_rn(v1.z - __bfloat162float(h3.x),
                                              v1.w - __bfloat162float(h3.y));
    hi = make_uint4(*(uint32_t*)&h0, *(uint32_t*)&h1, *(uint32_t*)&h2, *(uint32_t*)&h3);
    lo = make_uint4(*(uint32_t*)&l0, *(uint32_t*)&l1, *(uint32_t*)&l2, *(uint32_t*)&l3);
}

__global__ void __launch_bounds__(THREADS, 1) gemm_mma_kernel(
    const float* __restrict__ A, const unsigned* __restrict__ QW,
    const unsigned* __restrict__ QZ, const float* __restrict__ SC,
    float* __restrict__ C)
{
    extern __shared__ char smem[];
    const uint32_t sbase = smem_u32(smem);
    const int tid  = threadIdx.x;
    const int wid  = tid >> 5;
    const int lane = tid & 31;
    const int bm = blockIdx.y * BM;
    const int bn = blockIdx.x * BN;

    // warp tile: 64m x 32n, warp grid 2(m) x 4(n)
    const int wm = (wid & 1) * 64;
    const int wn = (wid >> 1) * 32;

    // ---- loader index precompute ----
    const int am   = tid >> 3;          // A row base 0..31 (+32*i)
    const int aks  = tid & 7;           // A k-chunk (8 floats)
    const int bw   = tid & 15;          // B n-octet/word index 0..15
    const int bk0  = tid >> 4;          // B k base 0..15 (+16*r)
    float* scS = (float*)(smem + OFF_SC);

    float acc[4][4][4];
    #pragma unroll
    for (int i = 0; i < 4; i++)
        #pragma unroll
        for (int j = 0; j < 4; j++)
            #pragma unroll
            for (int e = 0; e < 4; e++) acc[i][j][e] = 0.f;

    // ---- stage scales into smem (32 groups x 128 n) ----
    #pragma unroll
    for (int r = 0; r < 4; r++) {
        const int idx = tid + r * 256;          // 0..1023 float4 slots
        const int g = idx >> 5, v = idx & 31;
        const float4 s4 = *reinterpret_cast<const float4*>(
            SC + (size_t)g * N_TOT + bn + v * 4);
        *reinterpret_cast<float4*>(scS + g * 128 + v * 4) = s4;
    }

    // ---- prefetch registers ----
    float4 pa[4][2];
    unsigned qwr[4], qzr;

    auto prefetch = [&](int chunk) {
        const int k0 = chunk * BK;
        #pragma unroll
        for (int i = 0; i < 4; i++) {
            const float* ap = A + (size_t)(bm + am + 32 * i) * K_TOT + k0 + aks * 8;
            pa[i][0] = *reinterpret_cast<const float4*>(ap);
            pa[i][1] = *reinterpret_cast<const float4*>(ap + 4);
        }
        const int g = chunk >> 1;
        qzr = QZ[(size_t)g * QWC + (bn >> 3) + bw];
        #pragma unroll
        for (int r = 0; r < 4; r++)
            qwr[r] = QW[(size_t)(k0 + bk0 + 16 * r) * QWC + (bn >> 3) + bw];
    };

    auto convert_sts = [&](int s, int g) {
        char* stg = smem + s * STG_BYTES;
        // A tile: [m][k] rows of 128B, chunk swizzle
        #pragma unroll
        for (int i = 0; i < 4; i++) {
            const int m = am + 32 * i;
            uint4 hi, lo;
            cvt_hilo(pa[i][0], pa[i][1], hi, lo);
            const int off = m * 128 + ((aks ^ (m & 7)) << 4);
            *reinterpret_cast<uint4*>(stg + OFF_AH + off) = hi;
            *reinterpret_cast<uint4*>(stg + OFF_AL + off) = lo;
        }
        // B tile: [k][n] rows of 256B, chunk swizzle; scale+zero folded
        float s8[8], zs8[8];
        {
            const float* sp = scS + g * 128 + bw * 8;
            float4 sa = *reinterpret_cast<const float4*>(sp);
            float4 sb = *reinterpret_cast<const float4*>(sp + 4);
            s8[0]=sa.x; s8[1]=sa.y; s8[2]=sa.z; s8[3]=sa.w;
            s8[4]=sb.x; s8[5]=sb.y; s8[6]=sb.z; s8[7]=sb.w;
            #pragma unroll
            for (int j = 0; j < 8; j++)
                zs8[j] = s8[j] * (float)((qzr >> (4 * j)) & 15u);
        }
        #pragma unroll
        for (int r = 0; r < 4; r++) {
            const int k = bk0 + 16 * r;
            const unsigned q = qwr[r];
            float p[8];
            #pragma unroll
            for (int j = 0; j < 8; j++)
                p[j] = fmaf((float)((q >> (4 * j)) & 15u), s8[j], -zs8[j]);
            __nv_bfloat162 h0 = __floats2bfloat162_rn(p[0], p[1]);
            __nv_bfloat162 h1 = __floats2bfloat162_rn(p[2], p[3]);
            __nv_bfloat162 h2 = __floats2bfloat162_rn(p[4], p[5]);
            __nv_bfloat162 h3 = __floats2bfloat162_rn(p[6], p[7]);
            __nv_bfloat162 l0 = __floats2bfloat162_rn(p[0] - __bfloat162float(h0.x),
                                                      p[1] - __bfloat162float(h0.y));
            __nv_bfloat162 l1 = __floats2bfloat162_rn(p[2] - __bfloat162float(h1.x),
                                                      p[3] - __bfloat162float(h1.y));
            __nv_bfloat162 l2 = __floats2bfloat162_rn(p[4] - __bfloat162float(h2.x),
                                                      p[5] - __bfloat162float(h2.y));
            __nv_bfloat162 l3 = __floats2bfloat162_rn(p[6] - __bfloat162float(h3.x),
                                                      p[7] - __bfloat162float(h3.y));
            const int off = k * 256 + ((bw ^ (k & 7)) << 4);
            *reinterpret_cast<uint4*>(stg + OFF_BH + off) =
                make_uint4(*(uint32_t*)&h0, *(uint32_t*)&h1, *(uint32_t*)&h2, *(uint32_t*)&h3);
            *reinterpret_cast<uint4*>(stg + OFF_BL + off) =
                make_uint4(*(uint32_t*)&l0, *(uint32_t*)&l1, *(uint32_t*)&l2, *(uint32_t*)&l3);
        }
    };

    auto compute = [&](int s) {
        const uint32_t aH = sbase + s * STG_BYTES + OFF_AH;
        const uint32_t aL = sbase + s * STG_BYTES + OFF_AL;
        const uint32_t bH = sbase + s * STG_BYTES + OFF_BH;
        const uint32_t bL = sbase + s * STG_BYTES + OFF_BL;
        const int rsel = ((lane >> 3) & 1) * 8 + (lane & 7);
        const int hi8  = lane >> 4;
        const int l7   = lane & 7;
        #pragma unroll
        for (int ks = 0; ks < 4; ks++) {
            uint32_t ah[4][4], al[4][4], bh[4][2], bl[4][2];
            #pragma unroll
            for (int mi = 0; mi < 4; mi++) {
                const int m = wm + mi * 16 + rsel;
                const int off = m * 128 + (((ks * 2 + hi8) ^ l7) << 4);
                ldsm4(ah[mi], aH + off);
                ldsm4(al[mi], aL + off);
            }
            const int krow = ks * 16 + rsel;
            #pragma unroll
            for (int pr = 0; pr < 2; pr++) {
                const int ch = (wn >> 3) + pr * 2 + hi8;
                const int off = krow * 256 + ((ch ^ l7) << 4);
                uint32_t t[4];
                ldsm4t(t, bH + off);
                bh[pr*2][0]=t[0]; bh[pr*2][1]=t[1]; bh[pr*2+1][0]=t[2]; bh[pr*2+1][1]=t[3];
                ldsm4t(t, bL + off);
                bl[pr*2][0]=t[0]; bl[pr*2][1]=t[1]; bl[pr*2+1][0]=t[2]; bl[pr*2+1][1]=t[3];
            }
            #pragma unroll
            for (int mi = 0; mi < 4; mi++)
                #pragma unroll
                for (int nj = 0; nj < 4; nj++) {
                    mma_bf16(acc[mi][nj], ah[mi], bh[nj]);
                    mma_bf16(acc[mi][nj], ah[mi], bl[nj]);
                    mma_bf16(acc[mi][nj], al[mi], bh[nj]);
                }
        }
    };

    // ---- pipeline ----
    prefetch(0);
    __syncthreads();                 // scales visible
    convert_sts(0, 0);
    __syncthreads();

    for (int it = 0; it < NCH; ++it) {
        const int s = it & 1;
        if (it + 1 < NCH) prefetch(it + 1);
        compute(s);
        if (it + 1 < NCH) convert_sts(s ^ 1, (it + 1) >> 1);
        __syncthreads();
    }

    // ---- epilogue ----
    #pragma unroll
    for (int mi = 0; mi < 4; mi++)
        #pragma unroll
        for (int nj = 0; nj < 4; nj++) {
            const float* a = acc[mi][nj];
            const int row = bm + wm + mi * 16 + (lane >> 2);
            const int col = bn + wn + nj * 8 + (lane & 3) * 2;
            *reinterpret_cast<float2*>(&C[(size_t)row * N_TOT + col]) =
                make_float2(a[0], a[1]);
            *reinterpret_cast<float2*>(&C[(size_t)(row + 8) * N_TOT + col]) =
                make_float2(a[2], a[3]);
        }
}

extern "C" void kernel_launch(void* const* d_in, const int* in_sizes, int n_in,
                              void* d_out, int out_size)
{
    const float*    A  = (const float*)d_in[0];
    const unsigned* QW = (const unsigned*)d_in[1];
    const unsigned* QZ = (const unsigned*)d_in[2];
    const float*    SC = (const float*)d_in[3];
    float*          C  = (float*)d_out;

    cudaFuncSetAttribute(gemm_mma_kernel,
                         cudaFuncAttributeMaxDynamicSharedMemorySize, SMEM_TOTAL);
    dim3 grid(N_TOT / BN, M_TOT / BM);   // (86, 32)
    gemm_mma_kernel<<<grid, THREADS, SMEM_TOTAL>>>(A, QW, QZ, SC, C);
}

// round 5
// speedup vs baseline: 3.3942x; 1.9887x over previous
#include <cuda_runtime.h>
#include <cuda_bf16.h>
#include <cstdint>

#define M_TOT 4096
#define N_TOT 11008
#define K_TOT 4096
#define QWC   1376            // N_TOT/8 packed words per k-row

#define BM 128
#define BN 128
#define BK 64
#define NCH (K_TOT / BK)      // 64
#define THREADS 256

// dynamic smem layout (bytes)
#define STG_BYTES 49152
#define OFF_AH 0
#define OFF_AL 16384
#define OFF_B  32768
#define OFF_SC 98304                  // 32 groups x 128 n floats = 16KB
#define SMEM_TOTAL (98304 + 16384)    // 114688

// bf16 integer-bias trick: 0x4300 = 128.0, mantissa ulp = 1 at this exponent,
// so (0x4300 | nib) == 128 + nib EXACTLY (nib in [0,15]).
#define BIAS2 0x43004300u

__device__ __forceinline__ uint32_t smem_u32(const void* p) {
    uint32_t a;
    asm("{ .reg .u64 t; cvta.to.shared.u64 t, %1; cvt.u32.u64 %0, t; }"
        : "=r"(a) : "l"(p));
    return a;
}

__device__ __forceinline__ void ldsm4(uint32_t* r, uint32_t addr) {
    asm volatile("ldmatrix.sync.aligned.m8n8.x4.shared.b16 {%0,%1,%2,%3}, [%4];"
                 : "=r"(r[0]), "=r"(r[1]), "=r"(r[2]), "=r"(r[3]) : "r"(addr));
}
__device__ __forceinline__ void ldsm4t(uint32_t* r, uint32_t addr) {
    asm volatile("ldmatrix.sync.aligned.m8n8.x4.trans.shared.b16 {%0,%1,%2,%3}, [%4];"
                 : "=r"(r[0]), "=r"(r[1]), "=r"(r[2]), "=r"(r[3]) : "r"(addr));
}
__device__ __forceinline__ void mma_bf16(float* d, const uint32_t* a, const uint32_t* b) {
    asm volatile(
        "mma.sync.aligned.m16n8k16.row.col.f32.bf16.bf16.f32 "
        "{%0,%1,%2,%3}, {%4,%5,%6,%7}, {%8,%9}, {%0,%1,%2,%3};"
        : "+f"(d[0]), "+f"(d[1]), "+f"(d[2]), "+f"(d[3])
        : "r"(a[0]), "r"(a[1]), "r"(a[2]), "r"(a[3]), "r"(b[0]), "r"(b[1]));
}

// pack 8 floats (one 16B smem chunk) into bf16 hi + bf16 lo uint4s
__device__ __forceinline__ void cvt_hilo(const float4& v0, const float4& v1,
                                         uint4& hi, uint4& lo) {
    __nv_bfloat162 h0 = __floats2bfloat162_rn(v0.x, v0.y);
    __nv_bfloat162 h1 = __floats2bfloat162_rn(v0.z, v0.w);
    __nv_bfloat162 h2 = __floats2bfloat162_rn(v1.x, v1.y);
    __nv_bfloat162 h3 = __floats2bfloat162_rn(v1.z, v1.w);
    __nv_bfloat162 l0 = __floats2bfloat162_rn(v0.x - __bfloat162float(h0.x),
                                              v0.y - __bfloat162float(h0.y));
    __nv_bfloat162 l1 = __floats2bfloat162_rn(v0.z - __bfloat162float(h1.x),
                                              v0.w - __bfloat162float(h1.y));
    __nv_bfloat162 l2 = __floats2bfloat162_rn(v1.x - __bfloat162float(h2.x),
                                              v1.y - __bfloat162float(h2.y));
    __nv_bfloat162 l3 = __floats2bfloat162_rn(v1.z - __bfloat162float(h3.x),
                                              v1.w - __bfloat162float(h3.y));
    hi = make_uint4(*(uint32_t*)&h0, *(uint32_t*)&h1, *(uint32_t*)&h2, *(uint32_t*)&h3);
    lo = make_uint4(*(uint32_t*)&l0, *(uint32_t*)&l1, *(uint32_t*)&l2, *(uint32_t*)&l3);
}

__global__ void __launch_bounds__(THREADS, 1) gemm_mma_kernel(
    const float* __restrict__ A, const unsigned* __restrict__ QW,
    const unsigned* __restrict__ QZ, const float* __restrict__ SC,
    float* __restrict__ C)
{
    extern __shared__ char smem[];
    const uint32_t sbase = smem_u32(smem);
    const int tid  = threadIdx.x;
    const int wid  = tid >> 5;
    const int lane = tid & 31;
    const int bm = blockIdx.y * BM;
    const int bn = blockIdx.x * BN;

    // warp tile: 64m x 32n, warp grid 2(m) x 4(n)
    const int wm = (wid & 1) * 64;
    const int wn = (wid >> 1) * 32;

    // loader indices
    const int am   = tid >> 3;          // A row base 0..31 (+32*i)
    const int aks  = tid & 7;           // A k-octet (8 floats)
    const int bw   = tid & 15;          // B n-octet / packed-word index
    const int bk0  = tid >> 4;          // B k base 0..15 (+16*r)
    float* scS = (float*)(smem + OFF_SC);

    float accF[4][4][4];   // final, scaled
    float accG[4][4][4];   // group-local, exact-int B
    #pragma unroll
    for (int i = 0; i < 4; i++)
        #pragma unroll
        for (int j = 0; j < 4; j++)
            #pragma unroll
            for (int e = 0; e < 4; e++) { accF[i][j][e] = 0.f; accG[i][j][e] = 0.f; }

    // stage scales into smem (32 groups x 128 n)
    #pragma unroll
    for (int r = 0; r < 4; r++) {
        const int idx = tid + r * 256;
        const int g = idx >> 5, v = idx & 31;
        const float4 s4 = *reinterpret_cast<const float4*>(
            SC + (size_t)g * N_TOT + bn + v * 4);
        *reinterpret_cast<float4*>(scS + g * 128 + v * 4) = s4;
    }

    float4 pa[4][2];
    unsigned qwr[4], qzr;

    auto prefetch = [&](int chunk) {
        const int k0 = chunk * BK;
        #pragma unroll
        for (int i = 0; i < 4; i++) {
            const float* ap = A + (size_t)(bm + am + 32 * i) * K_TOT + k0 + aks * 8;
            pa[i][0] = *reinterpret_cast<const float4*>(ap);
            pa[i][1] = *reinterpret_cast<const float4*>(ap + 4);
        }
        const int g = chunk >> 1;
        qzr = QZ[(size_t)g * QWC + (bn >> 3) + bw];
        #pragma unroll
        for (int r = 0; r < 4; r++)
            qwr[r] = QW[(size_t)(k0 + bk0 + 16 * r) * QWC + (bn >> 3) + bw];
    };

    auto convert_sts = [&](int s) {
        char* stg = smem + s * STG_BYTES;
        // A tile: [m][k] rows of 128B (64 bf16), hi/lo split, chunk swizzle
        #pragma unroll
        for (int i = 0; i < 4; i++) {
            const int m = am + 32 * i;
            uint4 hi, lo;
            cvt_hilo(pa[i][0], pa[i][1], hi, lo);
            const int off = m * 128 + ((aks ^ (m & 7)) << 4);
            *reinterpret_cast<uint4*>(stg + OFF_AH + off) = hi;
            *reinterpret_cast<uint4*>(stg + OFF_AL + off) = lo;
        }
        // B tile: exact q = nib - zp in bf16 via 0x4300-bias + hsub2
        uint32_t zz[4];
        #pragma unroll
        for (int p = 0; p < 4; p++) {
            const unsigned zq = qzr >> (8 * p);
            zz[p] = BIAS2 | (zq & 0xFu) | ((zq & 0xF0u) << 12);
        }
        #pragma unroll
        for (int r = 0; r < 4; r++) {
            const int k = bk0 + 16 * r;
            const unsigned q = qwr[r];
            uint32_t w[4];
            #pragma unroll
            for (int p = 0; p < 4; p++) {
                const unsigned qq = q >> (8 * p);
                uint32_t u = BIAS2 | (qq & 0xFu) | ((qq & 0xF0u) << 12);
                __nv_bfloat162 d = __hsub2(*reinterpret_cast<__nv_bfloat162*>(&u),
                                           *reinterpret_cast<__nv_bfloat162*>(&zz[p]));
                w[p] = *reinterpret_cast<uint32_t*>(&d);
            }
            const int off = k * 256 + ((bw ^ (k & 7)) << 4);
            *reinterpret_cast<uint4*>(stg + OFF_B + off) =
                make_uint4(w[0], w[1], w[2], w[3]);
        }
    };

    auto compute = [&](int s) {
        const uint32_t aH = sbase + s * STG_BYTES + OFF_AH;
        const uint32_t aL = sbase + s * STG_BYTES + OFF_AL;
        const uint32_t bB = sbase + s * STG_BYTES + OFF_B;
        const int rsel = ((lane >> 3) & 1) * 8 + (lane & 7);
        const int hi8  = lane >> 4;
        const int l7   = lane & 7;
        #pragma unroll
        for (int ks = 0; ks < 4; ks++) {
            uint32_t ah[4][4], al[4][4], bq[4][2];
            #pragma unroll
            for (int mi = 0; mi < 4; mi++) {
                const int m = wm + mi * 16 + rsel;
                const int off = m * 128 + (((ks * 2 + hi8) ^ l7) << 4);
                ldsm4(ah[mi], aH + off);
                ldsm4(al[mi], aL + off);
            }
            const int krow = ks * 16 + rsel;
            #pragma unroll
            for (int pr = 0; pr < 2; pr++) {
                const int ch = (wn >> 3) + pr * 2 + hi8;
                const int off = krow * 256 + ((ch ^ l7) << 4);
                uint32_t t[4];
                ldsm4t(t, bB + off);
                bq[pr*2][0]=t[0]; bq[pr*2][1]=t[1]; bq[pr*2+1][0]=t[2]; bq[pr*2+1][1]=t[3];
            }
            #pragma unroll
            for (int mi = 0; mi < 4; mi++)
                #pragma unroll
                for (int nj = 0; nj < 4; nj++) {
                    mma_bf16(accG[mi][nj], ah[mi], bq[nj]);
                    mma_bf16(accG[mi][nj], al[mi], bq[nj]);
                }
        }
    };

    // pipeline
    prefetch(0);
    __syncthreads();                 // scales visible
    convert_sts(0);
    __syncthreads();

    for (int it = 0; it < NCH; ++it) {
        const int s = it & 1;
        if (it + 1 < NCH) prefetch(it + 1);
        compute(s);
        if (it + 1 < NCH) convert_sts(s ^ 1);
        // group rescale every 2 chunks (group = 128 k)
        if (it & 1) {
            const int g = it >> 1;
            #pragma unroll
            for (int nj = 0; nj < 4; nj++) {
                const float2 s2 = *reinterpret_cast<const float2*>(
                    scS + g * 128 + wn + nj * 8 + (lane & 3) * 2);
                #pragma unroll
                for (int mi = 0; mi < 4; mi++) {
                    accF[mi][nj][0] = fmaf(s2.x, accG[mi][nj][0], accF[mi][nj][0]);
                    accF[mi][nj][1] = fmaf(s2.y, accG[mi][nj][1], accF[mi][nj][1]);
                    accF[mi][nj][2] = fmaf(s2.x, accG[mi][nj][2], accF[mi][nj][2]);
                    accF[mi][nj][3] = fmaf(s2.y, accG[mi][nj][3], accF[mi][nj][3]);
                    accG[mi][nj][0] = 0.f; accG[mi][nj][1] = 0.f;
                    accG[mi][nj][2] = 0.f; accG[mi][nj][3] = 0.f;
                }
            }
        }
        __syncthreads();
    }

    // epilogue
    #pragma unroll
    for (int mi = 0; mi < 4; mi++)
        #pragma unroll
        for (int nj = 0; nj < 4; nj++) {
            const float* a = accF[mi][nj];
            const int row = bm + wm + mi * 16 + (lane >> 2);
            const int col = bn + wn + nj * 8 + (lane & 3) * 2;
            *reinterpret_cast<float2*>(&C[(size_t)row * N_TOT + col]) =
                make_float2(a[0], a[1]);
            *reinterpret_cast<float2*>(&C[(size_t)(row + 8) * N_TOT + col]) =
                make_float2(a[2], a[3]);
        }
}

extern "C" void kernel_launch(void* const* d_in, const int* in_sizes, int n_in,
                              void* d_out, int out_size)
{
    const float*    A  = (const float*)d_in[0];
    const unsigned* QW = (const unsigned*)d_in[1];
    const unsigned* QZ = (const unsigned*)d_in[2];
    const float*    SC = (const float*)d_in[3];
    float*          C  = (float*)d_out;

    cudaFuncSetAttribute(gemm_mma_kernel,
                         cudaFuncAttributeMaxDynamicSharedMemorySize, SMEM_TOTAL);
    dim3 grid(N_TOT / BN, M_TOT / BM);   // (86, 32)
    gemm_mma_kernel<<<grid, THREADS, SMEM_TOTAL>>>(A, QW, QZ, SC, C);
}

// round 6
// speedup vs baseline: 3.8263x; 1.1273x over previous
#include <cuda_runtime.h>
#include <cuda_bf16.h>
#include <cstdint>

#define M_TOT 4096
#define N_TOT 11008
#define K_TOT 4096
#define QWC   1376            // N_TOT/8 packed words per k-row

#define BM 128
#define BN 128
#define BK 64
#define NCH (K_TOT / BK)      // 64
#define THREADS 384           // 8 consumer warps + 4 producer warps
#define NSTAGE 3

// per-stage layout
#define STG_BYTES 49152
#define OFF_AH 0
#define OFF_AL 16384
#define OFF_B  32768
// smem map
#define OFF_BAR 0                         // 3 x (full,empty) pairs, 16B each
#define OFF_STG 1024
#define OFF_SC  (OFF_STG + NSTAGE * STG_BYTES)      // 148480
#define SMEM_TOTAL (OFF_SC + 16384)                 // 164864

// bf16 bias: 0x4300 = 128.0, ulp = 1 -> (0x4300|nib) == 128 + nib exactly
#define BIAS2 0x43004300u

__device__ __forceinline__ uint32_t smem_u32(const void* p) {
    uint32_t a;
    asm("{ .reg .u64 t; cvta.to.shared.u64 t, %1; cvt.u32.u64 %0, t; }"
        : "=r"(a) : "l"(p));
    return a;
}
__device__ __forceinline__ void ldsm4(uint32_t* r, uint32_t addr) {
    asm volatile("ldmatrix.sync.aligned.m8n8.x4.shared.b16 {%0,%1,%2,%3}, [%4];"
                 : "=r"(r[0]), "=r"(r[1]), "=r"(r[2]), "=r"(r[3]) : "r"(addr));
}
__device__ __forceinline__ void ldsm4t(uint32_t* r, uint32_t addr) {
    asm volatile("ldmatrix.sync.aligned.m8n8.x4.trans.shared.b16 {%0,%1,%2,%3}, [%4];"
                 : "=r"(r[0]), "=r"(r[1]), "=r"(r[2]), "=r"(r[3]) : "r"(addr));
}
__device__ __forceinline__ void mma_bf16(float* d, const uint32_t* a, const uint32_t* b) {
    asm volatile(
        "mma.sync.aligned.m16n8k16.row.col.f32.bf16.bf16.f32 "
        "{%0,%1,%2,%3}, {%4,%5,%6,%7}, {%8,%9}, {%0,%1,%2,%3};"
        : "+f"(d[0]), "+f"(d[1]), "+f"(d[2]), "+f"(d[3])
        : "r"(a[0]), "r"(a[1]), "r"(a[2]), "r"(a[3]), "r"(b[0]), "r"(b[1]));
}
__device__ __forceinline__ void mbar_init(uint32_t m, uint32_t c) {
    asm volatile("mbarrier.init.shared.b64 [%0], %1;" :: "r"(m), "r"(c) : "memory");
}
__device__ __forceinline__ void mbar_arrive(uint32_t m) {
    asm volatile("mbarrier.arrive.shared.b64 _, [%0];" :: "r"(m) : "memory");
}
__device__ __forceinline__ void mbar_wait(uint32_t m, uint32_t parity) {
    uint32_t done;
    asm volatile(
        "{\n\t.reg .pred p;\n\t"
        "mbarrier.try_wait.parity.acquire.cta.shared::cta.b64 p, [%1], %2;\n\t"
        "selp.b32 %0, 1, 0, p;\n\t}"
        : "=r"(done) : "r"(m), "r"(parity) : "memory");
    if (!done) {
        asm volatile(
            "{\n\t.reg .pred P1;\n\t"
            "WL_%=:\n\t"
            "mbarrier.try_wait.parity.acquire.cta.shared::cta.b64 P1, [%0], %1, 0x989680;\n\t"
            "@P1 bra.uni WD_%=;\n\t"
            "bra.uni WL_%=;\n\t"
            "WD_%=:\n\t}"
            :: "r"(m), "r"(parity) : "memory");
    }
}

__device__ __forceinline__ void cvt_hilo(const float4& v0, const float4& v1,
                                         uint4& hi, uint4& lo) {
    __nv_bfloat162 h0 = __floats2bfloat162_rn(v0.x, v0.y);
    __nv_bfloat162 h1 = __floats2bfloat162_rn(v0.z, v0.w);
    __nv_bfloat162 h2 = __floats2bfloat162_rn(v1.x, v1.y);
    __nv_bfloat162 h3 = __floats2bfloat162_rn(v1.z, v1.w);
    __nv_bfloat162 l0 = __floats2bfloat162_rn(v0.x - __bfloat162float(h0.x),
                                              v0.y - __bfloat162float(h0.y));
    __nv_bfloat162 l1 = __floats2bfloat162_rn(v0.z - __bfloat162float(h1.x),
                                              v0.w - __bfloat162float(h1.y));
    __nv_bfloat162 l2 = __floats2bfloat162_rn(v1.x - __bfloat162float(h2.x),
                                              v1.y - __bfloat162float(h2.y));
    __nv_bfloat162 l3 = __floats2bfloat162_rn(v1.z - __bfloat162float(h3.x),
                                              v1.w - __bfloat162float(h3.y));
    hi = make_uint4(*(uint32_t*)&h0, *(uint32_t*)&h1, *(uint32_t*)&h2, *(uint32_t*)&h3);
    lo = make_uint4(*(uint32_t*)&l0, *(uint32_t*)&l1, *(uint32_t*)&l2, *(uint32_t*)&l3);
}

__global__ void __launch_bounds__(THREADS, 1) gemm_ws_kernel(
    const float* __restrict__ A, const unsigned* __restrict__ QW,
    const unsigned* __restrict__ QZ, const float* __restrict__ SC,
    float* __restrict__ C)
{
    extern __shared__ char smem[];
    const uint32_t sbase = smem_u32(smem);
    const int tid  = threadIdx.x;
    const int wid  = tid >> 5;
    const int lane = tid & 31;
    const int bm = blockIdx.y * BM;
    const int bn = blockIdx.x * BN;
    float* scS = (float*)(smem + OFF_SC);

    // barriers: full[s] = sbase+OFF_BAR+16s, empty[s] = +8
    if (tid == 0) {
        #pragma unroll
        for (int s = 0; s < NSTAGE; s++) {
            mbar_init(sbase + OFF_BAR + 16 * s, 128);      // full: producer threads
            mbar_init(sbase + OFF_BAR + 16 * s + 8, 256);  // empty: consumer threads
        }
    }
    // stage scales (32 groups x 128 n = 1024 float4)
    for (int idx = tid; idx < 1024; idx += THREADS) {
        const int g = idx >> 5, v = idx & 31;
        *reinterpret_cast<float4*>(scS + g * 128 + v * 4) =
            *reinterpret_cast<const float4*>(SC + (size_t)g * N_TOT + bn + v * 4);
    }
    __syncthreads();

    if (wid >= 8) {
        // ================= PRODUCER (warps 8-11, 128 threads) =================
        const int ptid = tid - 256;
        const int am2 = ptid >> 3;     // row base 0..15 (+16*i)
        const int aks = ptid & 7;      // k-octet
        const int bw  = ptid & 15;     // n-octet / packed-word
        const int bkb = ptid >> 4;     // k base 0..7 (+8*r)
        int pe[NSTAGE] = {1, 1, 1};

        for (int it = 0; it < NCH; ++it) {
            const int s = (it == 0) ? 0 : (it % NSTAGE);
            mbar_wait(sbase + OFF_BAR + 16 * s + 8, pe[s]);
            pe[s] ^= 1;
            const int k0 = it * BK;

            // gather (high MLP)
            float4 va[8][2];
            #pragma unroll
            for (int i = 0; i < 8; i++) {
                const float* ap = A + (size_t)(bm + am2 + 16 * i) * K_TOT + k0 + aks * 8;
                va[i][0] = *reinterpret_cast<const float4*>(ap);
                va[i][1] = *reinterpret_cast<const float4*>(ap + 4);
            }
            const unsigned qz = QZ[(size_t)(it >> 1) * QWC + (bn >> 3) + bw];
            unsigned qw[8];
            #pragma unroll
            for (int r = 0; r < 8; r++)
                qw[r] = QW[(size_t)(k0 + bkb + 8 * r) * QWC + (bn >> 3) + bw];

            char* stg = smem + OFF_STG + s * STG_BYTES;
            // A hi/lo
            #pragma unroll
            for (int i = 0; i < 8; i++) {
                const int m = am2 + 16 * i;
                uint4 hi, lo;
                cvt_hilo(va[i][0], va[i][1], hi, lo);
                const int off = m * 128 + ((aks ^ (m & 7)) << 4);
                *reinterpret_cast<uint4*>(stg + OFF_AH + off) = hi;
                *reinterpret_cast<uint4*>(stg + OFF_AL + off) = lo;
            }
            // B exact int dequant
            uint32_t zz[4];
            #pragma unroll
            for (int p = 0; p < 4; p++) {
                const unsigned zq = qz >> (8 * p);
                zz[p] = BIAS2 | (zq & 0xFu) | ((zq & 0xF0u) << 12);
            }
            #pragma unroll
            for (int r = 0; r < 8; r++) {
                const int k = bkb + 8 * r;
                const unsigned q = qw[r];
                uint32_t w[4];
                #pragma unroll
                for (int p = 0; p < 4; p++) {
                    const unsigned qq = q >> (8 * p);
                    uint32_t u = BIAS2 | (qq & 0xFu) | ((qq & 0xF0u) << 12);
                    __nv_bfloat162 d = __hsub2(*reinterpret_cast<__nv_bfloat162*>(&u),
                                               *reinterpret_cast<__nv_bfloat162*>(&zz[p]));
                    w[p] = *reinterpret_cast<uint32_t*>(&d);
                }
                const int off = k * 256 + ((bw ^ (k & 7)) << 4);
                *reinterpret_cast<uint4*>(stg + OFF_B + off) =
                    make_uint4(w[0], w[1], w[2], w[3]);
            }
            mbar_arrive(sbase + OFF_BAR + 16 * s);   // full
        }
    } else {
        // ================= CONSUMER (warps 0-7, 256 threads) =================
        const int wm = (wid & 1) * 64;
        const int wn = (wid >> 1) * 32;
        const int rsel = ((lane >> 3) & 1) * 8 + (lane & 7);
        const int hi8  = lane >> 4;
        const int l7   = lane & 7;
        int cf[NSTAGE] = {0, 0, 0};

        float accF[4][4][4], accG[4][4][4];
        #pragma unroll
        for (int i = 0; i < 4; i++)
            #pragma unroll
            for (int j = 0; j < 4; j++)
                #pragma unroll
                for (int e = 0; e < 4; e++) { accF[i][j][e] = 0.f; accG[i][j][e] = 0.f; }

        for (int it = 0; it < NCH; ++it) {
            const int s = it % NSTAGE;
            mbar_wait(sbase + OFF_BAR + 16 * s, cf[s]);
            cf[s] ^= 1;

            const uint32_t base = sbase + OFF_STG + s * STG_BYTES;
            #pragma unroll
            for (int ks = 0; ks < 4; ks++) {
                uint32_t bq[4][2];
                const int krow = ks * 16 + rsel;
                #pragma unroll
                for (int pr = 0; pr < 2; pr++) {
                    const int ch = (wn >> 3) + pr * 2 + hi8;
                    const int off = krow * 256 + ((ch ^ l7) << 4);
                    uint32_t t[4];
                    ldsm4t(t, base + OFF_B + off);
                    bq[pr*2][0]=t[0]; bq[pr*2][1]=t[1];
                    bq[pr*2+1][0]=t[2]; bq[pr*2+1][1]=t[3];
                }
                #pragma unroll
                for (int mi = 0; mi < 4; mi++) {
                    const int m = wm + mi * 16 + rsel;
                    const int aoff = m * 128 + (((ks * 2 + hi8) ^ l7) << 4);
                    uint32_t ah[4];
                    ldsm4(ah, base + OFF_AH + aoff);
                    #pragma unroll
                    for (int nj = 0; nj < 4; nj++) mma_bf16(accG[mi][nj], ah, bq[nj]);
                    uint32_t al[4];
                    ldsm4(al, base + OFF_AL + aoff);
                    #pragma unroll
                    for (int nj = 0; nj < 4; nj++) mma_bf16(accG[mi][nj], al, bq[nj]);
                }
            }
            mbar_arrive(sbase + OFF_BAR + 16 * s + 8);   // empty

            if (it & 1) {
                const int g = it >> 1;
                #pragma unroll
                for (int nj = 0; nj < 4; nj++) {
                    const float2 s2 = *reinterpret_cast<const float2*>(
                        scS + g * 128 + wn + nj * 8 + (lane & 3) * 2);
                    #pragma unroll
                    for (int mi = 0; mi < 4; mi++) {
                        accF[mi][nj][0] = fmaf(s2.x, accG[mi][nj][0], accF[mi][nj][0]);
                        accF[mi][nj][1] = fmaf(s2.y, accG[mi][nj][1], accF[mi][nj][1]);
                        accF[mi][nj][2] = fmaf(s2.x, accG[mi][nj][2], accF[mi][nj][2]);
                        accF[mi][nj][3] = fmaf(s2.y, accG[mi][nj][3], accF[mi][nj][3]);
                        accG[mi][nj][0] = 0.f; accG[mi][nj][1] = 0.f;
                        accG[mi][nj][2] = 0.f; accG[mi][nj][3] = 0.f;
                    }
                }
            }
        }

        // epilogue
        #pragma unroll
        for (int mi = 0; mi < 4; mi++)
            #pragma unroll
            for (int nj = 0; nj < 4; nj++) {
                const float* a = accF[mi][nj];
                const int row = bm + wm + mi * 16 + (lane >> 2);
                const int col = bn + wn + nj * 8 + (lane & 3) * 2;
                *reinterpret_cast<float2*>(&C[(size_t)row * N_TOT + col]) =
                    make_float2(a[0], a[1]);
                *reinterpret_cast<float2*>(&C[(size_t)(row + 8) * N_TOT + col]) =
                    make_float2(a[2], a[3]);
            }
    }
}

extern "C" void kernel_launch(void* const* d_in, const int* in_sizes, int n_in,
                              void* d_out, int out_size)
{
    const float*    A  = (const float*)d_in[0];
    const unsigned* QW = (const unsigned*)d_in[1];
    const unsigned* QZ = (const unsigned*)d_in[2];
    const float*    SC = (const float*)d_in[3];
    float*          C  = (float*)d_out;

    cudaFuncSetAttribute(gemm_ws_kernel,
                         cudaFuncAttributeMaxDynamicSharedMemorySize, SMEM_TOTAL);
    dim3 grid(N_TOT / BN, M_TOT / BM);   // (86, 32)
    gemm_ws_kernel<<<grid, THREADS, SMEM_TOTAL>>>(A, QW, QZ, SC, C);
}